// round 1
// baseline (speedup 1.0000x reference)
#include <cuda_runtime.h>

// Problem shapes (fixed by setup_inputs):
//   image: (3, 512, 512)  f32
//   x:     (16, 1, 512, 512) f32
//   W:     (9, 3, 3, 3)   f32
//   b:     (9,)           f32
//   out:   (16, 1, 512, 512) f32
//
// y[n,i,j] = sum_{di,dj} x[n, i+di-1, j+dj-1] * K[di*3+dj, i, j]   (zero pad)
// K[c,i,j] = b[c] + sum_{m,u,v} W[c,m,u,v] * image[m, i+u-1, j+v-1] (zero pad, cross-corr)

#define HH 512
#define WW 512
#define NB 16
#define TX 32
#define TY 8
#define HALO_W (TX + 2)
#define HALO_H (TY + 2)
#define PITCH (TX + 4)   // smem row pitch (pad)

__global__ __launch_bounds__(TX * TY)
void fused_dynconv_kernel(const float* __restrict__ image,
                          const float* __restrict__ x,
                          const float* __restrict__ Wt,
                          const float* __restrict__ bb,
                          float* __restrict__ y)
{
    __shared__ float Wsh[243];
    __shared__ float bsh[9];
    __shared__ float img[3][HALO_H][PITCH];
    __shared__ float xs[2][HALO_H][PITCH];

    const int tx = threadIdx.x;
    const int ty = threadIdx.y;
    const int tid = ty * TX + tx;
    const int j0 = blockIdx.x * TX;
    const int i0 = blockIdx.y * TY;

    // ---- load weights/bias ----
    if (tid < 243) Wsh[tid] = Wt[tid];
    if (tid < 9)   bsh[tid] = bb[tid];

    // ---- load 3-channel image halo tile (zero-padded) ----
    #pragma unroll 2
    for (int idx = tid; idx < 3 * HALO_H * HALO_W; idx += TX * TY) {
        int m = idx / (HALO_H * HALO_W);
        int r = idx % (HALO_H * HALO_W);
        int u = r / HALO_W;
        int v = r % HALO_W;
        int gi = i0 + u - 1;
        int gj = j0 + v - 1;
        float val = 0.0f;
        if (gi >= 0 && gi < HH && gj >= 0 && gj < WW)
            val = image[(m * HH + gi) * WW + gj];
        img[m][u][v] = val;
    }
    __syncthreads();

    // ---- compute per-pixel 3x3 kernel K[0..8] in registers ----
    float K[9];
    #pragma unroll
    for (int c = 0; c < 9; c++) K[c] = bsh[c];

    #pragma unroll
    for (int m = 0; m < 3; m++) {
        float p[9];
        #pragma unroll
        for (int u = 0; u < 3; u++)
            #pragma unroll
            for (int v = 0; v < 3; v++)
                p[u * 3 + v] = img[m][ty + u][tx + v];
        #pragma unroll
        for (int c = 0; c < 9; c++) {
            #pragma unroll
            for (int t = 0; t < 9; t++)
                K[c] = fmaf(Wsh[(c * 3 + m) * 9 + t], p[t], K[c]);
        }
    }

    // ---- apply to all 16 batch slices, double-buffered x tile ----
    // preload n = 0 into buf 0
    {
        #pragma unroll 2
        for (int idx = tid; idx < HALO_H * HALO_W; idx += TX * TY) {
            int u = idx / HALO_W;
            int v = idx % HALO_W;
            int gi = i0 + u - 1;
            int gj = j0 + v - 1;
            float val = 0.0f;
            if (gi >= 0 && gi < HH && gj >= 0 && gj < WW)
                val = x[(size_t)(0 * HH + gi) * WW + gj];
            xs[0][u][v] = val;
        }
    }

    int cur = 0;
    const int oi = i0 + ty;
    const int oj = j0 + tx;

    #pragma unroll 1
    for (int n = 0; n < NB; n++) {
        __syncthreads();   // buf 'cur' ready; previous compute done -> other buf reusable

        if (n + 1 < NB) {
            int nxt = cur ^ 1;
            #pragma unroll 2
            for (int idx = tid; idx < HALO_H * HALO_W; idx += TX * TY) {
                int u = idx / HALO_W;
                int v = idx % HALO_W;
                int gi = i0 + u - 1;
                int gj = j0 + v - 1;
                float val = 0.0f;
                if (gi >= 0 && gi < HH && gj >= 0 && gj < WW)
                    val = x[((size_t)(n + 1) * HH + gi) * WW + gj];
                xs[nxt][u][v] = val;
            }
        }

        float acc = 0.0f;
        #pragma unroll
        for (int di = 0; di < 3; di++)
            #pragma unroll
            for (int dj = 0; dj < 3; dj++)
                acc = fmaf(xs[cur][ty + di][tx + dj], K[di * 3 + dj], acc);

        y[((size_t)n * HH + oi) * WW + oj] = acc;
        cur ^= 1;
    }
}

extern "C" void kernel_launch(void* const* d_in, const int* in_sizes, int n_in,
                              void* d_out, int out_size)
{
    const float* image = (const float*)d_in[0];   // 3*512*512
    const float* x     = (const float*)d_in[1];   // 16*512*512
    const float* Wt    = (const float*)d_in[2];   // 9*3*3*3 = 243
    const float* bb    = (const float*)d_in[3];   // 9
    float* y = (float*)d_out;                     // 16*512*512

    dim3 block(TX, TY);
    dim3 grid(WW / TX, HH / TY);   // (16, 64) = 1024 blocks
    fused_dynconv_kernel<<<grid, block>>>(image, x, Wt, bb, y);
}

// round 2
// speedup vs baseline: 1.8045x; 1.8045x over previous
#include <cuda_runtime.h>

// Shapes (fixed):
//   image: (3, 512, 512) f32
//   x:     (16, 1, 512, 512) f32
//   W:     (9, 3, 3, 3) f32   b: (9,) f32
//   out:   (16, 1, 512, 512) f32
//
// K[c,i,j] = b[c] + sum_{m,u,v} W[c,m,u,v] * image[m, i+u-1, j+v-1]  (zero pad)
// y[n,i,j] = sum_{u,v} x[n, i+u-1, j+v-1] * K[u*3+v, i, j]           (zero pad)

#define HH 512
#define WW 512
#define NB 16
#define PLANE (HH * WW)

// Load a 6-wide row window [col0-1 .. col0+4] with zero padding.
__device__ __forceinline__ void load_row6(const float* __restrict__ base,
                                          bool rowok, bool leftok, bool rightok,
                                          float r[6])
{
    if (rowok) {
        float4 v = *(const float4*)base;          // cols col0..col0+3 (16B aligned)
        r[1] = v.x; r[2] = v.y; r[3] = v.z; r[4] = v.w;
        r[0] = leftok  ? base[-1] : 0.0f;
        r[5] = rightok ? base[4]  : 0.0f;
    } else {
        r[0] = r[1] = r[2] = r[3] = r[4] = r[5] = 0.0f;
    }
}

__global__ __launch_bounds__(128)
void fused_dynconv4(const float* __restrict__ image,
                    const float* __restrict__ x,
                    const float* __restrict__ Wt,
                    const float* __restrict__ bb,
                    float* __restrict__ y)
{
    // W transposed: Wtr[t*12 + c] = W[c*27 + t]  (t = m*9+u*3+v, c = output tap)
    // pad stride 12 so &Wtr[t*12] is 16B-aligned -> 2x LDS.128 + 1 LDS per tap.
    __shared__ float Wtr[27 * 12];
    __shared__ float bsh[9];

    const int tx = threadIdx.x;           // 0..31
    const int ty = threadIdx.y;           // 0..3
    const int tid = ty * 32 + tx;

    for (int idx = tid; idx < 243; idx += 128) {
        int c = idx / 27;
        int t = idx % 27;
        Wtr[t * 12 + c] = Wt[idx];
    }
    if (tid < 9) bsh[tid] = bb[tid];
    __syncthreads();   // the ONLY barrier in the kernel

    const int col0 = (blockIdx.x * 32 + tx) * 4;   // 4 pixels per thread, 16B aligned
    const int i    = blockIdx.y * 4 + ty;

    const bool rok0 = (i > 0);
    const bool rok2 = (i < HH - 1);
    const bool lok  = (col0 > 0);
    const bool rtok = (col0 < WW - 4);

    // ---------------- K stage: per-pixel 3x3 kernels for 4 pixels ----------------
    float K[36];   // K[c*4 + p], c = u*3+v tap, p = pixel 0..3
    #pragma unroll
    for (int c = 0; c < 9; c++) {
        float bc = bsh[c];
        K[c * 4 + 0] = bc; K[c * 4 + 1] = bc;
        K[c * 4 + 2] = bc; K[c * 4 + 3] = bc;
    }

    #pragma unroll
    for (int m = 0; m < 3; m++) {
        float r[3][6];
        const float* base = image + (size_t)(m * HH + i) * WW + col0;
        load_row6(base - WW, rok0, lok, rtok, r[0]);
        load_row6(base,      true, lok, rtok, r[1]);
        load_row6(base + WW, rok2, lok, rtok, r[2]);

        #pragma unroll
        for (int u = 0; u < 3; u++) {
            #pragma unroll
            for (int v = 0; v < 3; v++) {
                const int t = m * 9 + u * 3 + v;
                float4 w0 = *(const float4*)&Wtr[t * 12];
                float4 w1 = *(const float4*)&Wtr[t * 12 + 4];
                float  w8 = Wtr[t * 12 + 8];
                float wv[9] = {w0.x, w0.y, w0.z, w0.w, w1.x, w1.y, w1.z, w1.w, w8};
                #pragma unroll
                for (int c = 0; c < 9; c++) {
                    #pragma unroll
                    for (int p = 0; p < 4; p++)
                        K[c * 4 + p] = fmaf(wv[c], r[u][v + p], K[c * 4 + p]);
                }
            }
        }
    }

    // ---------------- apply stage: 16 batch slices, no barriers ----------------
    const float* xb = x + (size_t)i * WW + col0;
    float*       yb = y + (size_t)i * WW + col0;

    #pragma unroll 2
    for (int n = 0; n < NB; n++) {
        float r[3][6];
        load_row6(xb - WW, rok0, lok, rtok, r[0]);
        load_row6(xb,      true, lok, rtok, r[1]);
        load_row6(xb + WW, rok2, lok, rtok, r[2]);

        float acc0 = 0.f, acc1 = 0.f, acc2 = 0.f, acc3 = 0.f;
        #pragma unroll
        for (int u = 0; u < 3; u++) {
            #pragma unroll
            for (int v = 0; v < 3; v++) {
                const int c = u * 3 + v;
                acc0 = fmaf(r[u][v + 0], K[c * 4 + 0], acc0);
                acc1 = fmaf(r[u][v + 1], K[c * 4 + 1], acc1);
                acc2 = fmaf(r[u][v + 2], K[c * 4 + 2], acc2);
                acc3 = fmaf(r[u][v + 3], K[c * 4 + 3], acc3);
            }
        }
        float4 o; o.x = acc0; o.y = acc1; o.z = acc2; o.w = acc3;
        *(float4*)yb = o;

        xb += PLANE;
        yb += PLANE;
    }
}

extern "C" void kernel_launch(void* const* d_in, const int* in_sizes, int n_in,
                              void* d_out, int out_size)
{
    const float* image = (const float*)d_in[0];   // 3*512*512
    const float* x     = (const float*)d_in[1];   // 16*512*512
    const float* Wt    = (const float*)d_in[2];   // 243
    const float* bb    = (const float*)d_in[3];   // 9
    float* y = (float*)d_out;                     // 16*512*512

    dim3 block(32, 4);                 // 128 threads, each owns 4 horizontal pixels
    dim3 grid(WW / (32 * 4), HH / 4);  // (4, 128) = 512 blocks
    fused_dynconv4<<<grid, block>>>(image, x, Wt, bb, y);
}